// round 15
// baseline (speedup 1.0000x reference)
#include <cuda_runtime.h>
#include <math.h>

// ---------------------------------------------------------------------------
// Problem constants
// ---------------------------------------------------------------------------
#define B_    16
#define T_    64
#define HW_   512
#define E_    256
#define E2_   512
#define V_    128
#define BT_   1024   // B*T
#define NBLK_ 3

typedef unsigned long long ull;

// ---------------------------------------------------------------------------
// Scratch (device globals: no allocation allowed)
// ---------------------------------------------------------------------------
__device__ __align__(16) float g_s    [BT_ * E_];       // embed(labels), fixed
__device__ __align__(16) float g_a    [BT_ * E_];       // running activation (row-major)
__device__ __align__(16) float g_aT   [B_ * E_ * T_];   // a transposed [b][e][t]
__device__ __align__(16) float g_z    [BT_ * E_];       // GLU output
__device__ __align__(16) float g_res  [B_ * HW_ * E_];  // enc + dec
__device__ __align__(16) float g_Wt   [E_ * E_];        // W_w transposed: Wt[i][o]
__device__ __align__(16) float g_Wop  [E_ * V_];        // Wo interleaved e-pairs
__device__ __align__(16) float g_cw2  [3 * E_ * E2_];   // conv_w, GLU-interleaved cols
__device__ __align__(16) float g_cb2  [E2_];            // conv_b, interleaved
__device__ __align__(16) float g_decT [B_ * E_ * HW_];  // dec transposed [b][e][s]
__device__ __align__(16) float g_part [6 * BT_ * E2_];  // conv split-k partials
__device__ __align__(16) float g_hpart[8 * BT_ * E_];   // hproj split-k partials (8 slices)

// ---------------------------------------------------------------------------
// f32x2 packed math (sm_100+)
// ---------------------------------------------------------------------------
__device__ __forceinline__ ull pack2(float x, float y) {
    ull r; asm("mov.b64 %0, {%1,%2};" : "=l"(r) : "f"(x), "f"(y)); return r;
}
__device__ __forceinline__ void unpack2(ull v, float& x, float& y) {
    asm("mov.b64 {%0,%1}, %2;" : "=f"(x), "=f"(y) : "l"(v));
}
__device__ __forceinline__ ull ffma2(ull a, ull b, ull c) {
    ull d; asm("fma.rn.f32x2 %0, %1, %2, %3;" : "=l"(d) : "l"(a), "l"(b), "l"(c)); return d;
}

// ---------------------------------------------------------------------------
// K0: merged setup — embed | residual | weight-prep | dec transpose
// ---------------------------------------------------------------------------
#define NB_EMB  1024
#define NB_RES  2048
#define NB_PREP 1153
#define NB_TR   2048

__global__ __launch_bounds__(256) void k_setup(const int* __restrict__ labels,
                                               const float* __restrict__ emb,
                                               const float* __restrict__ enc,
                                               const float* __restrict__ dec,
                                               const float* __restrict__ Ww,
                                               const float* __restrict__ Wo,
                                               const float* __restrict__ cw,
                                               const float* __restrict__ cb) {
    int bid = blockIdx.x, tid = threadIdx.x;

    if (bid < NB_EMB) {
        int row = bid, e = tid;
        int lbl = labels[row];
        float v = emb[lbl * E_ + e];
        g_s[row * E_ + e] = v;
        g_a[row * E_ + e] = v;
        g_aT[(row >> 6) * (E_ * T_) + e * T_ + (row & 63)] = v;
        return;
    }
    bid -= NB_EMB;

    if (bid < NB_RES) {
        int i = bid * 256 + tid;
        float4 a = ((const float4*)enc)[i];
        float4 b = ((const float4*)dec)[i];
        float4 c;
        c.x = a.x + b.x; c.y = a.y + b.y; c.z = a.z + b.z; c.w = a.w + b.w;
        ((float4*)g_res)[i] = c;
        return;
    }
    bid -= NB_RES;

    if (bid < NB_PREP) {
        if (bid < E_) {
            g_Wt[tid * E_ + bid] = Ww[bid * E_ + tid];
        } else if (bid < E_ + V_) {
            int v = bid - E_;
            g_Wop[(tid >> 1) * (2 * V_) + 2 * v + (tid & 1)] = Wo[v * E_ + tid];
        } else if (bid < E_ + V_ + 3 * E_) {
            int kk = bid - (E_ + V_);
            #pragma unroll
            for (int h = 0; h < 2; ++h) {
                int c = tid + h * 256;
                int j = c >> 1, p = c & 1;
                g_cw2[kk * E2_ + c] = cw[kk * E2_ + p * E_ + j];
            }
        } else {
            #pragma unroll
            for (int h = 0; h < 2; ++h) {
                int c = tid + h * 256;
                int j = c >> 1, p = c & 1;
                g_cb2[c] = cb[p * E_ + j];
            }
        }
        return;
    }
    bid -= NB_PREP;

    // ---- transpose dec -> g_decT[b][e][s] ----
    {
        __shared__ float tile[32][33];
        int s0 = (bid & 15) << 5;
        int e0 = ((bid >> 4) & 7) << 5;
        int b  = bid >> 7;
        int tx = tid & 31, ty = tid >> 5;
        #pragma unroll
        for (int i = 0; i < 32; i += 8)
            tile[ty + i][tx] = dec[((b << 9) + s0 + ty + i) * E_ + e0 + tx];
        __syncthreads();
        #pragma unroll
        for (int i = 0; i < 32; i += 8)
            g_decT[((b << 8) + e0 + ty + i) * HW_ + s0 + tx] = tile[tx][ty + i];
    }
}

// ---------------------------------------------------------------------------
// K1: conv split-(k,ci-half) GEMM -> g_part[kk], kk = 2k + ci_half (0..5)
// grid 768 = kk(6) x b(16) x n-tile(8); 128 threads; thread tile 8m x 4n
// ---------------------------------------------------------------------------
__global__ __launch_bounds__(128) void k_conv5() {
    __shared__ __align__(16) float As[2][16][68];
    __shared__ __align__(16) float Bs[2][16][68];

    int bid = blockIdx.x;
    int nt  = bid & 7;
    int bb  = (bid >> 3) & 15;
    int kk  = bid >> 7;                  // 0..5
    int k   = kk >> 1;                   // conv tap 0..2
    int cib = (kk & 1) << 7;             // ci base: 0 or 128
    int n0  = nt << 6;

    int tid = threadIdx.x;
    int kcL = tid >> 3, qL = tid & 7;    // loader: kc row, 2 col-groups (qL, qL+8)
    int mi  = tid >> 4, ni = tid & 15;   // compute: 8m x 4n

    const float* aTb = g_aT + bb * (E_ * T_) + cib * T_;
    const float* wB  = g_cw2 + (k * E_ + cib) * E2_ + n0;

    // ---- prologue: chunk 0 (ci0 = 0) ----
    {
        #pragma unroll
        for (int h = 0; h < 2; ++h) {
            int col = 4 * qL + 32 * h;
            float4 va = *(const float4*)&aTb[kcL * T_ + col];
            float4 vb = *(const float4*)&wB[kcL * E2_ + col];
            *(float4*)&Bs[0][kcL][col] = vb;
            float av[4] = {va.x, va.y, va.z, va.w};
            int mb = col + 1 - k;
            #pragma unroll
            for (int j = 0; j < 4; ++j) {
                int m = mb + j;
                if ((unsigned)m < 64u) As[0][kcL][m] = av[j];
            }
        }
        if (qL == 0) {
            if (k == 0) As[0][kcL][0]  = 0.f;
            if (k == 2) As[0][kcL][63] = 0.f;
        }
    }
    __syncthreads();

    ull acc[4][4];
    #pragma unroll
    for (int p = 0; p < 4; ++p)
        #pragma unroll
        for (int j = 0; j < 4; ++j) acc[p][j] = pack2(0.f, 0.f);

    float4 vaN[2], vbN[2];
    for (int ch = 0; ch < 8; ++ch) {
        int cur = ch & 1;
        if (ch < 7) {
            int ci0 = (ch + 1) << 4;
            #pragma unroll
            for (int h = 0; h < 2; ++h) {
                int col = 4 * qL + 32 * h;
                vaN[h] = *(const float4*)&aTb[(ci0 + kcL) * T_ + col];
                vbN[h] = *(const float4*)&wB[(ci0 + kcL) * E2_ + col];
            }
        }

        #pragma unroll
        for (int kc = 0; kc < 16; ++kc) {
            ulonglong2 a01 = *(const ulonglong2*)&As[cur][kc][8 * mi];
            ulonglong2 a23 = *(const ulonglong2*)&As[cur][kc][8 * mi + 4];
            float4     bv  = *(const float4*)    &Bs[cur][kc][4 * ni];
            ull b0 = pack2(bv.x, bv.x);
            ull b1 = pack2(bv.y, bv.y);
            ull b2 = pack2(bv.z, bv.z);
            ull b3 = pack2(bv.w, bv.w);
            acc[0][0] = ffma2(a01.x, b0, acc[0][0]);
            acc[0][1] = ffma2(a01.x, b1, acc[0][1]);
            acc[0][2] = ffma2(a01.x, b2, acc[0][2]);
            acc[0][3] = ffma2(a01.x, b3, acc[0][3]);
            acc[1][0] = ffma2(a01.y, b0, acc[1][0]);
            acc[1][1] = ffma2(a01.y, b1, acc[1][1]);
            acc[1][2] = ffma2(a01.y, b2, acc[1][2]);
            acc[1][3] = ffma2(a01.y, b3, acc[1][3]);
            acc[2][0] = ffma2(a23.x, b0, acc[2][0]);
            acc[2][1] = ffma2(a23.x, b1, acc[2][1]);
            acc[2][2] = ffma2(a23.x, b2, acc[2][2]);
            acc[2][3] = ffma2(a23.x, b3, acc[2][3]);
            acc[3][0] = ffma2(a23.y, b0, acc[3][0]);
            acc[3][1] = ffma2(a23.y, b1, acc[3][1]);
            acc[3][2] = ffma2(a23.y, b2, acc[3][2]);
            acc[3][3] = ffma2(a23.y, b3, acc[3][3]);
        }

        if (ch < 7) {
            int nxt = cur ^ 1;
            #pragma unroll
            for (int h = 0; h < 2; ++h) {
                int col = 4 * qL + 32 * h;
                *(float4*)&Bs[nxt][kcL][col] = vbN[h];
                float av[4] = {vaN[h].x, vaN[h].y, vaN[h].z, vaN[h].w};
                int mb = col + 1 - k;
                #pragma unroll
                for (int j = 0; j < 4; ++j) {
                    int m = mb + j;
                    if ((unsigned)m < 64u) As[nxt][kcL][m] = av[j];
                }
            }
            if (qL == 0) {
                if (k == 0) As[nxt][kcL][0]  = 0.f;
                if (k == 2) As[nxt][kcL][63] = 0.f;
            }
        }
        __syncthreads();
    }

    // ---- epilogue: write partials (float4 rows) ----
    float* pb = g_part + (size_t)kk * BT_ * E2_ + ((bb << 6) + 8 * mi) * E2_ + n0 + 4 * ni;
    #pragma unroll
    for (int p = 0; p < 4; ++p) {
        float l0, h0, l1, h1, l2, h2, l3, h3;
        unpack2(acc[p][0], l0, h0);
        unpack2(acc[p][1], l1, h1);
        unpack2(acc[p][2], l2, h2);
        unpack2(acc[p][3], l3, h3);
        float* r0 = pb + (2 * p) * E2_;
        *(float4*)r0         = make_float4(l0, l1, l2, l3);
        *(float4*)(r0 + E2_) = make_float4(h0, h1, h2, h3);
    }
}

// ---------------------------------------------------------------------------
// K1b: reduce 6 partials + bias + GLU -> g_z
// ---------------------------------------------------------------------------
__global__ __launch_bounds__(256) void k_glu() {
    int row = blockIdx.x, j = threadIdx.x;
    size_t off = (size_t)row * E2_ + 2 * j;
    float za, zb;
    {
        float2 p = *(const float2*)&g_part[off];
        za = p.x; zb = p.y;
    }
    #pragma unroll
    for (int kk = 1; kk < 6; ++kk) {
        float2 p = *(const float2*)&g_part[off + (size_t)kk * BT_ * E2_];
        za += p.x; zb += p.y;
    }
    float2 bb = *(const float2*)&g_cb2[2 * j];
    za += bb.x; zb += bb.y;
    g_z[row * E_ + j] = za / (1.f + expf(-zb));
}

// ---------------------------------------------------------------------------
// K2a: h partials: split-K GEMM  C[row][o] += z[row][k-8th] @ Wt[k-8th][o]
// grid 512 = kq(8) x row-tile(16 of 64) x o-tile(4 of 64); 128 threads
// K per CTA = 32 (2 chunks); thread tile 8m x 4n (crossbar-balanced)
// ---------------------------------------------------------------------------
__global__ __launch_bounds__(128) void k_hgemm() {
    __shared__ __align__(16) float As[2][16][68];
    __shared__ __align__(16) float Bs[2][16][68];

    int bid  = blockIdx.x;
    int ot   = bid & 3;
    int rt   = (bid >> 2) & 15;
    int kq   = bid >> 6;                 // 0..7
    int row0 = rt << 6;
    int o0   = ot << 6;
    int k0   = kq << 5;                  // K slice of 32

    int tid = threadIdx.x;
    int mA  = tid >> 1, qA = tid & 1;    // A loader: row mA, kc-groups 4qA, 4qA+8
    int kcL = tid >> 3, qL = tid & 7;    // B loader: kc row, col-groups 4qL, 4qL+32
    int mi  = tid >> 4, ni = tid & 15;   // compute: 8m x 4n

    const float* zb = g_z + row0 * E_ + k0;
    const float* wB = g_Wt + k0 * E_ + o0;

    // ---- prologue: chunk 0 ----
    {
        #pragma unroll
        for (int h = 0; h < 2; ++h) {
            int kc0 = 4 * qA + 8 * h;
            float4 va = *(const float4*)&zb[mA * E_ + kc0];
            As[0][kc0 + 0][mA] = va.x;
            As[0][kc0 + 1][mA] = va.y;
            As[0][kc0 + 2][mA] = va.z;
            As[0][kc0 + 3][mA] = va.w;
            int col = 4 * qL + 32 * h;
            float4 vb = *(const float4*)&wB[kcL * E_ + col];
            *(float4*)&Bs[0][kcL][col] = vb;
        }
    }
    __syncthreads();

    ull acc[4][4];
    #pragma unroll
    for (int p = 0; p < 4; ++p)
        #pragma unroll
        for (int j = 0; j < 4; ++j) acc[p][j] = pack2(0.f, 0.f);

    float4 vaN[2], vbN[2];
    #pragma unroll
    for (int ch = 0; ch < 2; ++ch) {
        int cur = ch & 1;
        if (ch < 1) {
            int ci0 = 16;
            #pragma unroll
            for (int h = 0; h < 2; ++h) {
                vaN[h] = *(const float4*)&zb[mA * E_ + ci0 + 4 * qA + 8 * h];
                vbN[h] = *(const float4*)&wB[(ci0 + kcL) * E_ + 4 * qL + 32 * h];
            }
        }

        #pragma unroll
        for (int kc = 0; kc < 16; ++kc) {
            ulonglong2 a01 = *(const ulonglong2*)&As[cur][kc][8 * mi];
            ulonglong2 a23 = *(const ulonglong2*)&As[cur][kc][8 * mi + 4];
            float4     bv  = *(const float4*)    &Bs[cur][kc][4 * ni];
            ull b0 = pack2(bv.x, bv.x);
            ull b1 = pack2(bv.y, bv.y);
            ull b2 = pack2(bv.z, bv.z);
            ull b3 = pack2(bv.w, bv.w);
            acc[0][0] = ffma2(a01.x, b0, acc[0][0]);
            acc[0][1] = ffma2(a01.x, b1, acc[0][1]);
            acc[0][2] = ffma2(a01.x, b2, acc[0][2]);
            acc[0][3] = ffma2(a01.x, b3, acc[0][3]);
            acc[1][0] = ffma2(a01.y, b0, acc[1][0]);
            acc[1][1] = ffma2(a01.y, b1, acc[1][1]);
            acc[1][2] = ffma2(a01.y, b2, acc[1][2]);
            acc[1][3] = ffma2(a01.y, b3, acc[1][3]);
            acc[2][0] = ffma2(a23.x, b0, acc[2][0]);
            acc[2][1] = ffma2(a23.x, b1, acc[2][1]);
            acc[2][2] = ffma2(a23.x, b2, acc[2][2]);
            acc[2][3] = ffma2(a23.x, b3, acc[2][3]);
            acc[3][0] = ffma2(a23.y, b0, acc[3][0]);
            acc[3][1] = ffma2(a23.y, b1, acc[3][1]);
            acc[3][2] = ffma2(a23.y, b2, acc[3][2]);
            acc[3][3] = ffma2(a23.y, b3, acc[3][3]);
        }

        if (ch < 1) {
            int nxt = cur ^ 1;
            #pragma unroll
            for (int h = 0; h < 2; ++h) {
                int kc0 = 4 * qA + 8 * h;
                As[nxt][kc0 + 0][mA] = vaN[h].x;
                As[nxt][kc0 + 1][mA] = vaN[h].y;
                As[nxt][kc0 + 2][mA] = vaN[h].z;
                As[nxt][kc0 + 3][mA] = vaN[h].w;
                *(float4*)&Bs[nxt][kcL][4 * qL + 32 * h] = vbN[h];
            }
        }
        __syncthreads();
    }

    float* pb = g_hpart + (size_t)kq * BT_ * E_ + (row0 + 8 * mi) * E_ + o0 + 4 * ni;
    #pragma unroll
    for (int p = 0; p < 4; ++p) {
        float l0, h0, l1, h1, l2, h2, l3, h3;
        unpack2(acc[p][0], l0, h0);
        unpack2(acc[p][1], l1, h1);
        unpack2(acc[p][2], l2, h2);
        unpack2(acc[p][3], l3, h3);
        float* r0 = pb + (2 * p) * E_;
        *(float4*)r0        = make_float4(l0, l1, l2, l3);
        *(float4*)(r0 + E_) = make_float4(h0, h1, h2, h3);
    }
}

// ---------------------------------------------------------------------------
// K2b: fused attention: h-finalize (8 partials) | scores | softmax | ctx | a=c+z
// grid 128 (8 t-rows per CTA); 512 threads
// ---------------------------------------------------------------------------
__global__ __launch_bounds__(512) void k_attn3(const float* __restrict__ Wb) {
    __shared__ __align__(16) float qt  [E_][8];     // h queries [e][t]   (8 KB)
    __shared__ __align__(16) float sst [HW_][8];    // scores/exp [s][t] (16 KB)
    __shared__ __align__(16) float psum[E_][8];     // ctx partial half-1 (8 KB)
    __shared__ float redM[8][2], redS[8][2], Iv[8];

    int row0 = blockIdx.x << 3;          // 8 rows, never crosses b (64 | 8)
    int b    = row0 >> 6;
    int t0   = row0 & 63;
    int tid  = threadIdx.x;
    int lane = tid & 31;
    int w    = tid >> 5;                 // 0..15
    int e    = tid & 255;
    int half = tid >> 8;                 // 0/1

    // ---- phase 0: fused h finalize: qt[e][r] = Σ(8) hpart + Wb + s ----
    {
        float wb = Wb[e];
        #pragma unroll
        for (int j = 0; j < 4; ++j) {
            int r = half * 4 + j;
            size_t o = (size_t)(row0 + r) * E_ + e;
            float h = g_hpart[o];
            #pragma unroll
            for (int kq = 1; kq < 8; ++kq)
                h += g_hpart[(size_t)kq * BT_ * E_ + o];
            qt[e][r] = h + wb + g_s[o];
        }
    }
    __syncthreads();

    // ---- phase 1: scores (thread = s = tid) ----
    {
        const float* kb = g_decT + ((size_t)b << 8) * HW_ + tid;
        ull A[4];
        #pragma unroll
        for (int j = 0; j < 4; ++j) A[j] = pack2(0.f, 0.f);

        #pragma unroll 16
        for (int ei = 0; ei < E_; ++ei) {
            float kv = kb[ei * HW_];
            ull kp = pack2(kv, kv);
            ulonglong2 q01 = *(const ulonglong2*)&qt[ei][0];
            ulonglong2 q23 = *(const ulonglong2*)&qt[ei][4];
            A[0] = ffma2(q01.x, kp, A[0]);
            A[1] = ffma2(q01.y, kp, A[1]);
            A[2] = ffma2(q23.x, kp, A[2]);
            A[3] = ffma2(q23.y, kp, A[3]);
        }
        ull* sp = (ull*)&sst[tid][0];
        #pragma unroll
        for (int j = 0; j < 4; ++j) sp[j] = A[j];
    }
    __syncthreads();

    // ---- phase 2: softmax stats (warp w: t = w&7, s-half = w>>3) ----
    {
        int t  = w & 7;
        int sh = (w >> 3) << 8;
        float m = -1e30f;
        #pragma unroll
        for (int k = 0; k < 8; ++k)
            m = fmaxf(m, sst[sh + k * 32 + lane][t]);
        #pragma unroll
        for (int off = 16; off; off >>= 1)
            m = fmaxf(m, __shfl_xor_sync(0xffffffffu, m, off));
        if (lane == 0) redM[t][w >> 3] = m;
        __syncthreads();
        float M = fmaxf(redM[t][0], redM[t][1]);

        float sum = 0.f;
        #pragma unroll
        for (int k = 0; k < 8; ++k) {
            int s = sh + k * 32 + lane;
            float ev = expf(sst[s][t] - M);
            sst[s][t] = ev;
            sum += ev;
        }
        #pragma unroll
        for (int off = 16; off; off >>= 1)
            sum += __shfl_xor_sync(0xffffffffu, sum, off);
        if (lane == 0) redS[t][w >> 3] = sum;
        __syncthreads();
        if (tid < 8) Iv[tid] = 1.f / (redS[tid][0] + redS[tid][1]);
    }
    __syncthreads();

    // ---- phase 3: ctx: thread (e, half) accumulates its 256-s half ----
    {
        const float* resb = g_res + ((size_t)b * HW_ + (half << 8)) * E_ + e;
        int sb = half << 8;
        ull acc[4];
        #pragma unroll
        for (int p = 0; p < 4; ++p) acc[p] = pack2(0.f, 0.f);

        #pragma unroll 8
        for (int s = 0; s < 256; ++s) {
            float rv = resb[(size_t)s * E_];
            ull rp = pack2(rv, rv);
            ulonglong2 a01 = *(const ulonglong2*)&sst[sb + s][0];
            ulonglong2 a23 = *(const ulonglong2*)&sst[sb + s][4];
            acc[0] = ffma2(a01.x, rp, acc[0]);
            acc[1] = ffma2(a01.y, rp, acc[1]);
            acc[2] = ffma2(a23.x, rp, acc[2]);
            acc[3] = ffma2(a23.y, rp, acc[3]);
        }

        if (half == 1) {
            ull* pp = (ull*)&psum[e][0];
            #pragma unroll
            for (int p = 0; p < 4; ++p) pp[p] = acc[p];
        }
        __syncthreads();

        if (half == 0) {
            float av8[8];
            #pragma unroll
            for (int p = 0; p < 4; ++p) {
                float c0, c1; unpack2(acc[p], c0, c1);
                int t = 2 * p;
                size_t idx = (size_t)(row0 + t) * E_ + e;
                float v0 = (c0 + psum[e][t])     * Iv[t]     + g_z[idx];
                float v1 = (c1 + psum[e][t + 1]) * Iv[t + 1] + g_z[idx + E_];
                g_a[idx]      = v0;
                g_a[idx + E_] = v1;
                av8[t] = v0; av8[t + 1] = v1;
            }
            float* atp = g_aT + b * (E_ * T_) + e * T_ + t0;
            *(float4*)atp       = make_float4(av8[0], av8[1], av8[2], av8[3]);
            *(float4*)(atp + 4) = make_float4(av8[4], av8[5], av8[6], av8[7]);
        }
    }
}

// ---------------------------------------------------------------------------
// K3: logits = a @ Wo^T + Wo_b; log_softmax over V  -> out
// ---------------------------------------------------------------------------
__global__ __launch_bounds__(128) void k_logits(const float* __restrict__ Wob,
                                                float* __restrict__ out) {
    __shared__ __align__(16) float av4[4][E_];
    __shared__ float redm[4][4], reds[4][4];

    int row0 = blockIdx.x * 4;
    int v    = threadIdx.x;
    int lane = v & 31;
    int wid  = v >> 5;

    #pragma unroll
    for (int r = 0; r < 4; ++r) {
        av4[r][v]       = g_a[(row0 + r) * E_ + v];
        av4[r][v + 128] = g_a[(row0 + r) * E_ + v + 128];
    }
    __syncthreads();

    ull acc[4];
    #pragma unroll
    for (int r = 0; r < 4; ++r) acc[r] = pack2(0.f, 0.f);

    const ull* wop = (const ull*)g_Wop;
    #pragma unroll 4
    for (int ep = 0; ep < E_ / 2; ++ep) {
        ull wp = wop[ep * V_ + v];
        #pragma unroll
        for (int r = 0; r < 4; ++r)
            acc[r] = ffma2(((const ull*)av4[r])[ep], wp, acc[r]);
    }

    float lg[4], wb = Wob[v];
    #pragma unroll
    for (int r = 0; r < 4; ++r) {
        float lo, hi; unpack2(acc[r], lo, hi);
        lg[r] = lo + hi + wb;
    }

    float wm[4];
    #pragma unroll
    for (int r = 0; r < 4; ++r) {
        wm[r] = lg[r];
        #pragma unroll
        for (int off = 16; off; off >>= 1)
            wm[r] = fmaxf(wm[r], __shfl_xor_sync(0xffffffffu, wm[r], off));
    }
    if (lane == 0) {
        #pragma unroll
        for (int r = 0; r < 4; ++r) redm[r][wid] = wm[r];
    }
    __syncthreads();
    float bm[4];
    #pragma unroll
    for (int r = 0; r < 4; ++r)
        bm[r] = fmaxf(fmaxf(redm[r][0], redm[r][1]), fmaxf(redm[r][2], redm[r][3]));

    float ws[4];
    #pragma unroll
    for (int r = 0; r < 4; ++r) {
        ws[r] = expf(lg[r] - bm[r]);
        #pragma unroll
        for (int off = 16; off; off >>= 1)
            ws[r] += __shfl_xor_sync(0xffffffffu, ws[r], off);
    }
    if (lane == 0) {
        #pragma unroll
        for (int r = 0; r < 4; ++r) reds[r][wid] = ws[r];
    }
    __syncthreads();

    #pragma unroll
    for (int r = 0; r < 4; ++r) {
        float bs = reds[r][0] + reds[r][1] + reds[r][2] + reds[r][3];
        out[(row0 + r) * V_ + v] = lg[r] - bm[r] - logf(bs);
    }
}

// ---------------------------------------------------------------------------
// kernel_launch
// ---------------------------------------------------------------------------
extern "C" void kernel_launch(void* const* d_in, const int* in_sizes, int n_in,
                              void* d_out, int out_size) {
    int li = 2;
    for (int i = 0; i < n_in; ++i)
        if (in_sizes[i] == 1024) { li = i; break; }

    const float *enc, *dec, *emb, *cw, *cb, *Ww, *Wb, *Wo, *Wob;
    const int* labels;
    if (li == 2) {
        enc = (const float*)d_in[0]; dec = (const float*)d_in[1];
        labels = (const int*)d_in[2];
        emb = (const float*)d_in[3]; cw  = (const float*)d_in[4];
        cb  = (const float*)d_in[5]; Ww  = (const float*)d_in[6];
        Wb  = (const float*)d_in[7]; Wo  = (const float*)d_in[8];
        Wob = (const float*)d_in[9];
    } else {
        enc = (const float*)d_in[0]; dec = (const float*)d_in[1];
        emb = (const float*)d_in[2]; cw  = (const float*)d_in[3];
        cb  = (const float*)d_in[4]; Ww  = (const float*)d_in[5];
        Wb  = (const float*)d_in[6]; Wo  = (const float*)d_in[7];
        Wob = (const float*)d_in[8];
        labels = (const int*)d_in[9];
    }
    float* out = (float*)d_out;

    k_setup<<<NB_EMB + NB_RES + NB_PREP + NB_TR, 256>>>(labels, emb, enc, dec,
                                                        Ww, Wo, cw, cb);

    for (int l = 0; l < NBLK_; ++l) {
        k_conv5<<<768, 128>>>();
        k_glu  <<<BT_, 256>>>();
        k_hgemm<<<512, 128>>>();
        k_attn3<<<128, 512>>>(Wb);
    }

    k_logits<<<BT_ / 4, 128>>>(Wob, out);
}

// round 16
// speedup vs baseline: 1.0393x; 1.0393x over previous
#include <cuda_runtime.h>
#include <math.h>

// ---------------------------------------------------------------------------
// Problem constants
// ---------------------------------------------------------------------------
#define B_    16
#define T_    64
#define HW_   512
#define E_    256
#define E2_   512
#define V_    128
#define BT_   1024   // B*T
#define NBLK_ 3

typedef unsigned long long ull;

// ---------------------------------------------------------------------------
// Scratch (device globals: no allocation allowed)
// ---------------------------------------------------------------------------
__device__ __align__(16) float g_s    [BT_ * E_];       // embed(labels), fixed
__device__ __align__(16) float g_a    [BT_ * E_];       // running activation (row-major)
__device__ __align__(16) float g_aT   [B_ * E_ * T_];   // a transposed [b][e][t]
__device__ __align__(16) float g_z    [BT_ * E_];       // GLU output
__device__ __align__(16) float g_res  [B_ * HW_ * E_];  // enc + dec
__device__ __align__(16) float g_Wt   [E_ * E_];        // W_w transposed: Wt[i][o]
__device__ __align__(16) float g_Wop  [E_ * V_];        // Wo interleaved e-pairs
__device__ __align__(16) float g_cw2  [3 * E_ * E2_];   // conv_w, GLU-interleaved cols
__device__ __align__(16) float g_cb2  [E2_];            // conv_b, interleaved
__device__ __align__(16) float g_decT [B_ * E_ * HW_];  // dec transposed [b][e][s]
__device__ __align__(16) float g_part [6 * BT_ * E2_];  // conv split-k partials
__device__ __align__(16) float g_hpart[4 * BT_ * E_];   // hproj split-k partials

// ---------------------------------------------------------------------------
// f32x2 packed math (sm_100+)
// ---------------------------------------------------------------------------
__device__ __forceinline__ ull pack2(float x, float y) {
    ull r; asm("mov.b64 %0, {%1,%2};" : "=l"(r) : "f"(x), "f"(y)); return r;
}
__device__ __forceinline__ void unpack2(ull v, float& x, float& y) {
    asm("mov.b64 {%0,%1}, %2;" : "=f"(x), "=f"(y) : "l"(v));
}
__device__ __forceinline__ ull ffma2(ull a, ull b, ull c) {
    ull d; asm("fma.rn.f32x2 %0, %1, %2, %3;" : "=l"(d) : "l"(a), "l"(b), "l"(c)); return d;
}

// ---------------------------------------------------------------------------
// K0: merged setup — embed | residual | weight-prep | dec transpose
// ---------------------------------------------------------------------------
#define NB_EMB  1024
#define NB_RES  2048
#define NB_PREP 1153
#define NB_TR   2048

__global__ __launch_bounds__(256) void k_setup(const int* __restrict__ labels,
                                               const float* __restrict__ emb,
                                               const float* __restrict__ enc,
                                               const float* __restrict__ dec,
                                               const float* __restrict__ Ww,
                                               const float* __restrict__ Wo,
                                               const float* __restrict__ cw,
                                               const float* __restrict__ cb) {
    int bid = blockIdx.x, tid = threadIdx.x;

    if (bid < NB_EMB) {
        int row = bid, e = tid;
        int lbl = labels[row];
        float v = emb[lbl * E_ + e];
        g_s[row * E_ + e] = v;
        g_a[row * E_ + e] = v;
        g_aT[(row >> 6) * (E_ * T_) + e * T_ + (row & 63)] = v;
        return;
    }
    bid -= NB_EMB;

    if (bid < NB_RES) {
        int i = bid * 256 + tid;
        float4 a = ((const float4*)enc)[i];
        float4 b = ((const float4*)dec)[i];
        float4 c;
        c.x = a.x + b.x; c.y = a.y + b.y; c.z = a.z + b.z; c.w = a.w + b.w;
        ((float4*)g_res)[i] = c;
        return;
    }
    bid -= NB_RES;

    if (bid < NB_PREP) {
        if (bid < E_) {
            g_Wt[tid * E_ + bid] = Ww[bid * E_ + tid];
        } else if (bid < E_ + V_) {
            int v = bid - E_;
            g_Wop[(tid >> 1) * (2 * V_) + 2 * v + (tid & 1)] = Wo[v * E_ + tid];
        } else if (bid < E_ + V_ + 3 * E_) {
            int kk = bid - (E_ + V_);
            #pragma unroll
            for (int h = 0; h < 2; ++h) {
                int c = tid + h * 256;
                int j = c >> 1, p = c & 1;
                g_cw2[kk * E2_ + c] = cw[kk * E2_ + p * E_ + j];
            }
        } else {
            #pragma unroll
            for (int h = 0; h < 2; ++h) {
                int c = tid + h * 256;
                int j = c >> 1, p = c & 1;
                g_cb2[c] = cb[p * E_ + j];
            }
        }
        return;
    }
    bid -= NB_PREP;

    // ---- transpose dec -> g_decT[b][e][s] ----
    {
        __shared__ float tile[32][33];
        int s0 = (bid & 15) << 5;
        int e0 = ((bid >> 4) & 7) << 5;
        int b  = bid >> 7;
        int tx = tid & 31, ty = tid >> 5;
        #pragma unroll
        for (int i = 0; i < 32; i += 8)
            tile[ty + i][tx] = dec[((b << 9) + s0 + ty + i) * E_ + e0 + tx];
        __syncthreads();
        #pragma unroll
        for (int i = 0; i < 32; i += 8)
            g_decT[((b << 8) + e0 + ty + i) * HW_ + s0 + tx] = tile[tx][ty + i];
    }
}

// ---------------------------------------------------------------------------
// K1: conv split-(k,ci-half) GEMM -> g_part[kk], kk = 2k + ci_half (0..5)
// grid 384 = kk(6) x b(16) x n-pair(4); 256 threads; thread tile 8m x 4n
// Two 64-col n-tiles per CTA share the A smem tile (A LDG traffic halved).
// ---------------------------------------------------------------------------
__global__ __launch_bounds__(256) void k_conv6() {
    __shared__ __align__(16) float As[2][16][68];
    __shared__ __align__(16) float Bs[2][16][132];

    int bid = blockIdx.x;
    int nt2 = bid & 3;
    int bb  = (bid >> 2) & 15;
    int kk  = bid >> 6;                  // 0..5
    int k   = kk >> 1;                   // conv tap 0..2
    int cib = (kk & 1) << 7;             // ci base: 0 or 128
    int n0  = nt2 << 7;                  // 128-col pair base

    int tid = threadIdx.x;
    int kcA = tid >> 4, qA = tid & 15;   // A loader: kc row, col-group 4qA
    int mi  = tid >> 5, ni = tid & 31;   // compute: 8m x 4n (n over 128 cols)

    const float* aTb = g_aT + bb * (E_ * T_) + cib * T_;
    const float* wB  = g_cw2 + (k * E_ + cib) * E2_ + n0;

    int colA = 4 * qA;
    int mb   = colA + 1 - k;

    // ---- prologue: chunk 0 (ci0 = 0) ----
    {
        float4 va = *(const float4*)&aTb[kcA * T_ + colA];
        float av[4] = {va.x, va.y, va.z, va.w};
        #pragma unroll
        for (int j = 0; j < 4; ++j) {
            int m = mb + j;
            if ((unsigned)m < 64u) As[0][kcA][m] = av[j];
        }
        if (qA == 0) {
            if (k == 0) As[0][kcA][0]  = 0.f;
            if (k == 2) As[0][kcA][63] = 0.f;
        }
        #pragma unroll
        for (int h = 0; h < 2; ++h) {
            int col = colA + 64 * h;
            float4 vb = *(const float4*)&wB[kcA * E2_ + col];
            *(float4*)&Bs[0][kcA][col] = vb;
        }
    }
    __syncthreads();

    ull acc[4][4];
    #pragma unroll
    for (int p = 0; p < 4; ++p)
        #pragma unroll
        for (int j = 0; j < 4; ++j) acc[p][j] = pack2(0.f, 0.f);

    float4 vaN, vbN[2];
    for (int ch = 0; ch < 8; ++ch) {
        int cur = ch & 1;
        if (ch < 7) {
            int ci0 = (ch + 1) << 4;
            vaN = *(const float4*)&aTb[(ci0 + kcA) * T_ + colA];
            #pragma unroll
            for (int h = 0; h < 2; ++h)
                vbN[h] = *(const float4*)&wB[(ci0 + kcA) * E2_ + colA + 64 * h];
        }

        #pragma unroll
        for (int kc = 0; kc < 16; ++kc) {
            ulonglong2 a01 = *(const ulonglong2*)&As[cur][kc][8 * mi];
            ulonglong2 a23 = *(const ulonglong2*)&As[cur][kc][8 * mi + 4];
            float4     bv  = *(const float4*)    &Bs[cur][kc][4 * ni];
            ull b0 = pack2(bv.x, bv.x);
            ull b1 = pack2(bv.y, bv.y);
            ull b2 = pack2(bv.z, bv.z);
            ull b3 = pack2(bv.w, bv.w);
            acc[0][0] = ffma2(a01.x, b0, acc[0][0]);
            acc[0][1] = ffma2(a01.x, b1, acc[0][1]);
            acc[0][2] = ffma2(a01.x, b2, acc[0][2]);
            acc[0][3] = ffma2(a01.x, b3, acc[0][3]);
            acc[1][0] = ffma2(a01.y, b0, acc[1][0]);
            acc[1][1] = ffma2(a01.y, b1, acc[1][1]);
            acc[1][2] = ffma2(a01.y, b2, acc[1][2]);
            acc[1][3] = ffma2(a01.y, b3, acc[1][3]);
            acc[2][0] = ffma2(a23.x, b0, acc[2][0]);
            acc[2][1] = ffma2(a23.x, b1, acc[2][1]);
            acc[2][2] = ffma2(a23.x, b2, acc[2][2]);
            acc[2][3] = ffma2(a23.x, b3, acc[2][3]);
            acc[3][0] = ffma2(a23.y, b0, acc[3][0]);
            acc[3][1] = ffma2(a23.y, b1, acc[3][1]);
            acc[3][2] = ffma2(a23.y, b2, acc[3][2]);
            acc[3][3] = ffma2(a23.y, b3, acc[3][3]);
        }

        if (ch < 7) {
            int nxt = cur ^ 1;
            float av[4] = {vaN.x, vaN.y, vaN.z, vaN.w};
            #pragma unroll
            for (int j = 0; j < 4; ++j) {
                int m = mb + j;
                if ((unsigned)m < 64u) As[nxt][kcA][m] = av[j];
            }
            if (qA == 0) {
                if (k == 0) As[nxt][kcA][0]  = 0.f;
                if (k == 2) As[nxt][kcA][63] = 0.f;
            }
            #pragma unroll
            for (int h = 0; h < 2; ++h)
                *(float4*)&Bs[nxt][kcA][colA + 64 * h] = vbN[h];
        }
        __syncthreads();
    }

    // ---- epilogue: write partials (float4 rows) ----
    float* pb = g_part + (size_t)kk * BT_ * E2_ + ((bb << 6) + 8 * mi) * E2_ + n0 + 4 * ni;
    #pragma unroll
    for (int p = 0; p < 4; ++p) {
        float l0, h0, l1, h1, l2, h2, l3, h3;
        unpack2(acc[p][0], l0, h0);
        unpack2(acc[p][1], l1, h1);
        unpack2(acc[p][2], l2, h2);
        unpack2(acc[p][3], l3, h3);
        float* r0 = pb + (2 * p) * E2_;
        *(float4*)r0         = make_float4(l0, l1, l2, l3);
        *(float4*)(r0 + E2_) = make_float4(h0, h1, h2, h3);
    }
}

// ---------------------------------------------------------------------------
// K1b: reduce 6 partials + bias + GLU -> g_z
// ---------------------------------------------------------------------------
__global__ __launch_bounds__(256) void k_glu() {
    int row = blockIdx.x, j = threadIdx.x;
    size_t off = (size_t)row * E2_ + 2 * j;
    float za, zb;
    {
        float2 p = *(const float2*)&g_part[off];
        za = p.x; zb = p.y;
    }
    #pragma unroll
    for (int kk = 1; kk < 6; ++kk) {
        float2 p = *(const float2*)&g_part[off + (size_t)kk * BT_ * E2_];
        za += p.x; zb += p.y;
    }
    float2 bb = *(const float2*)&g_cb2[2 * j];
    za += bb.x; zb += bb.y;
    g_z[row * E_ + j] = za / (1.f + expf(-zb));
}

// ---------------------------------------------------------------------------
// K2a: h partials: split-K GEMM  C[row][o] += z[row][k-qtr] @ Wt[k-qtr][o]
// grid 256 = kq(4) x row-tile(16 of 64) x o-tile(4 of 64); 128 threads
// thread tile 8m x 4n (R13 configuration — best measured)
// ---------------------------------------------------------------------------
__global__ __launch_bounds__(128) void k_hgemm() {
    __shared__ __align__(16) float As[2][16][68];
    __shared__ __align__(16) float Bs[2][16][68];

    int bid  = blockIdx.x;
    int ot   = bid & 3;
    int rt   = (bid >> 2) & 15;
    int kq   = bid >> 6;                 // 0..3
    int row0 = rt << 6;
    int o0   = ot << 6;
    int k0   = kq << 6;

    int tid = threadIdx.x;
    int mA  = tid >> 1, qA = tid & 1;    // A loader: row mA, kc-groups 4qA, 4qA+8
    int kcL = tid >> 3, qL = tid & 7;    // B loader: kc row, col-groups 4qL, 4qL+32
    int mi  = tid >> 4, ni = tid & 15;   // compute: 8m x 4n

    const float* zb = g_z + row0 * E_ + k0;
    const float* wB = g_Wt + k0 * E_ + o0;

    // ---- prologue: chunk 0 ----
    {
        #pragma unroll
        for (int h = 0; h < 2; ++h) {
            int kc0 = 4 * qA + 8 * h;
            float4 va = *(const float4*)&zb[mA * E_ + kc0];
            As[0][kc0 + 0][mA] = va.x;
            As[0][kc0 + 1][mA] = va.y;
            As[0][kc0 + 2][mA] = va.z;
            As[0][kc0 + 3][mA] = va.w;
            int col = 4 * qL + 32 * h;
            float4 vb = *(const float4*)&wB[kcL * E_ + col];
            *(float4*)&Bs[0][kcL][col] = vb;
        }
    }
    __syncthreads();

    ull acc[4][4];
    #pragma unroll
    for (int p = 0; p < 4; ++p)
        #pragma unroll
        for (int j = 0; j < 4; ++j) acc[p][j] = pack2(0.f, 0.f);

    float4 vaN[2], vbN[2];
    #pragma unroll
    for (int ch = 0; ch < 4; ++ch) {
        int cur = ch & 1;
        if (ch < 3) {
            int ci0 = (ch + 1) << 4;
            #pragma unroll
            for (int h = 0; h < 2; ++h) {
                vaN[h] = *(const float4*)&zb[mA * E_ + ci0 + 4 * qA + 8 * h];
                vbN[h] = *(const float4*)&wB[(ci0 + kcL) * E_ + 4 * qL + 32 * h];
            }
        }

        #pragma unroll
        for (int kc = 0; kc < 16; ++kc) {
            ulonglong2 a01 = *(const ulonglong2*)&As[cur][kc][8 * mi];
            ulonglong2 a23 = *(const ulonglong2*)&As[cur][kc][8 * mi + 4];
            float4     bv  = *(const float4*)    &Bs[cur][kc][4 * ni];
            ull b0 = pack2(bv.x, bv.x);
            ull b1 = pack2(bv.y, bv.y);
            ull b2 = pack2(bv.z, bv.z);
            ull b3 = pack2(bv.w, bv.w);
            acc[0][0] = ffma2(a01.x, b0, acc[0][0]);
            acc[0][1] = ffma2(a01.x, b1, acc[0][1]);
            acc[0][2] = ffma2(a01.x, b2, acc[0][2]);
            acc[0][3] = ffma2(a01.x, b3, acc[0][3]);
            acc[1][0] = ffma2(a01.y, b0, acc[1][0]);
            acc[1][1] = ffma2(a01.y, b1, acc[1][1]);
            acc[1][2] = ffma2(a01.y, b2, acc[1][2]);
            acc[1][3] = ffma2(a01.y, b3, acc[1][3]);
            acc[2][0] = ffma2(a23.x, b0, acc[2][0]);
            acc[2][1] = ffma2(a23.x, b1, acc[2][1]);
            acc[2][2] = ffma2(a23.x, b2, acc[2][2]);
            acc[2][3] = ffma2(a23.x, b3, acc[2][3]);
            acc[3][0] = ffma2(a23.y, b0, acc[3][0]);
            acc[3][1] = ffma2(a23.y, b1, acc[3][1]);
            acc[3][2] = ffma2(a23.y, b2, acc[3][2]);
            acc[3][3] = ffma2(a23.y, b3, acc[3][3]);
        }

        if (ch < 3) {
            int nxt = cur ^ 1;
            #pragma unroll
            for (int h = 0; h < 2; ++h) {
                int kc0 = 4 * qA + 8 * h;
                As[nxt][kc0 + 0][mA] = vaN[h].x;
                As[nxt][kc0 + 1][mA] = vaN[h].y;
                As[nxt][kc0 + 2][mA] = vaN[h].z;
                As[nxt][kc0 + 3][mA] = vaN[h].w;
                *(float4*)&Bs[nxt][kcL][4 * qL + 32 * h] = vbN[h];
            }
        }
        __syncthreads();
    }

    float* pb = g_hpart + (size_t)kq * BT_ * E_ + (row0 + 8 * mi) * E_ + o0 + 4 * ni;
    #pragma unroll
    for (int p = 0; p < 4; ++p) {
        float l0, h0, l1, h1, l2, h2, l3, h3;
        unpack2(acc[p][0], l0, h0);
        unpack2(acc[p][1], l1, h1);
        unpack2(acc[p][2], l2, h2);
        unpack2(acc[p][3], l3, h3);
        float* r0 = pb + (2 * p) * E_;
        *(float4*)r0        = make_float4(l0, l1, l2, l3);
        *(float4*)(r0 + E_) = make_float4(h0, h1, h2, h3);
    }
}

// ---------------------------------------------------------------------------
// K2b: fused attention: h-finalize | scores | softmax | ctx | a=c+z
// grid 128 (8 t-rows per CTA); 512 threads
// ---------------------------------------------------------------------------
__global__ __launch_bounds__(512) void k_attn3(const float* __restrict__ Wb) {
    __shared__ __align__(16) float qt  [E_][8];     // h queries [e][t]   (8 KB)
    __shared__ __align__(16) float sst [HW_][8];    // scores/exp [s][t] (16 KB)
    __shared__ __align__(16) float psum[E_][8];     // ctx partial half-1 (8 KB)
    __shared__ float redM[8][2], redS[8][2], Iv[8];

    int row0 = blockIdx.x << 3;          // 8 rows, never crosses b (64 | 8)
    int b    = row0 >> 6;
    int t0   = row0 & 63;
    int tid  = threadIdx.x;
    int lane = tid & 31;
    int w    = tid >> 5;                 // 0..15
    int e    = tid & 255;
    int half = tid >> 8;                 // 0/1

    // ---- phase 0: fused h finalize: qt[e][r] = Σ hpart + Wb + s ----
    {
        float wb = Wb[e];
        #pragma unroll
        for (int j = 0; j < 4; ++j) {
            int r = half * 4 + j;
            size_t o = (size_t)(row0 + r) * E_ + e;
            float h = g_hpart[o]
                    + g_hpart[(size_t)BT_ * E_ + o]
                    + g_hpart[(size_t)2 * BT_ * E_ + o]
                    + g_hpart[(size_t)3 * BT_ * E_ + o]
                    + wb + g_s[o];
            qt[e][r] = h;
        }
    }
    __syncthreads();

    // ---- phase 1: scores (thread = s = tid) ----
    {
        const float* kb = g_decT + ((size_t)b << 8) * HW_ + tid;
        ull A[4];
        #pragma unroll
        for (int j = 0; j < 4; ++j) A[j] = pack2(0.f, 0.f);

        #pragma unroll 16
        for (int ei = 0; ei < E_; ++ei) {
            float kv = kb[ei * HW_];
            ull kp = pack2(kv, kv);
            ulonglong2 q01 = *(const ulonglong2*)&qt[ei][0];
            ulonglong2 q23 = *(const ulonglong2*)&qt[ei][4];
            A[0] = ffma2(q01.x, kp, A[0]);
            A[1] = ffma2(q01.y, kp, A[1]);
            A[2] = ffma2(q23.x, kp, A[2]);
            A[3] = ffma2(q23.y, kp, A[3]);
        }
        ull* sp = (ull*)&sst[tid][0];
        #pragma unroll
        for (int j = 0; j < 4; ++j) sp[j] = A[j];
    }
    __syncthreads();

    // ---- phase 2: softmax stats (warp w: t = w&7, s-half = w>>3) ----
    {
        int t  = w & 7;
        int sh = (w >> 3) << 8;
        float m = -1e30f;
        #pragma unroll
        for (int k = 0; k < 8; ++k)
            m = fmaxf(m, sst[sh + k * 32 + lane][t]);
        #pragma unroll
        for (int off = 16; off; off >>= 1)
            m = fmaxf(m, __shfl_xor_sync(0xffffffffu, m, off));
        if (lane == 0) redM[t][w >> 3] = m;
        __syncthreads();
        float M = fmaxf(redM[t][0], redM[t][1]);

        float sum = 0.f;
        #pragma unroll
        for (int k = 0; k < 8; ++k) {
            int s = sh + k * 32 + lane;
            float ev = expf(sst[s][t] - M);
            sst[s][t] = ev;
            sum += ev;
        }
        #pragma unroll
        for (int off = 16; off; off >>= 1)
            sum += __shfl_xor_sync(0xffffffffu, sum, off);
        if (lane == 0) redS[t][w >> 3] = sum;
        __syncthreads();
        if (tid < 8) Iv[tid] = 1.f / (redS[tid][0] + redS[tid][1]);
    }
    __syncthreads();

    // ---- phase 3: ctx: thread (e, half) accumulates its 256-s half ----
    {
        const float* resb = g_res + ((size_t)b * HW_ + (half << 8)) * E_ + e;
        int sb = half << 8;
        ull acc[4];
        #pragma unroll
        for (int p = 0; p < 4; ++p) acc[p] = pack2(0.f, 0.f);

        #pragma unroll 8
        for (int s = 0; s < 256; ++s) {
            float rv = resb[(size_t)s * E_];
            ull rp = pack2(rv, rv);
            ulonglong2 a01 = *(const ulonglong2*)&sst[sb + s][0];
            ulonglong2 a23 = *(const ulonglong2*)&sst[sb + s][4];
            acc[0] = ffma2(a01.x, rp, acc[0]);
            acc[1] = ffma2(a01.y, rp, acc[1]);
            acc[2] = ffma2(a23.x, rp, acc[2]);
            acc[3] = ffma2(a23.y, rp, acc[3]);
        }

        if (half == 1) {
            ull* pp = (ull*)&psum[e][0];
            #pragma unroll
            for (int p = 0; p < 4; ++p) pp[p] = acc[p];
        }
        __syncthreads();

        if (half == 0) {
            float av8[8];
            #pragma unroll
            for (int p = 0; p < 4; ++p) {
                float c0, c1; unpack2(acc[p], c0, c1);
                int t = 2 * p;
                size_t idx = (size_t)(row0 + t) * E_ + e;
                float v0 = (c0 + psum[e][t])     * Iv[t]     + g_z[idx];
                float v1 = (c1 + psum[e][t + 1]) * Iv[t + 1] + g_z[idx + E_];
                g_a[idx]      = v0;
                g_a[idx + E_] = v1;
                av8[t] = v0; av8[t + 1] = v1;
            }
            float* atp = g_aT + b * (E_ * T_) + e * T_ + t0;
            *(float4*)atp       = make_float4(av8[0], av8[1], av8[2], av8[3]);
            *(float4*)(atp + 4) = make_float4(av8[4], av8[5], av8[6], av8[7]);
        }
    }
}

// ---------------------------------------------------------------------------
// K3: logits = a @ Wo^T + Wo_b; log_softmax over V  -> out
// ---------------------------------------------------------------------------
__global__ __launch_bounds__(128) void k_logits(const float* __restrict__ Wob,
                                                float* __restrict__ out) {
    __shared__ __align__(16) float av4[4][E_];
    __shared__ float redm[4][4], reds[4][4];

    int row0 = blockIdx.x * 4;
    int v    = threadIdx.x;
    int lane = v & 31;
    int wid  = v >> 5;

    #pragma unroll
    for (int r = 0; r < 4; ++r) {
        av4[r][v]       = g_a[(row0 + r) * E_ + v];
        av4[r][v + 128] = g_a[(row0 + r) * E_ + v + 128];
    }
    __syncthreads();

    ull acc[4];
    #pragma unroll
    for (int r = 0; r < 4; ++r) acc[r] = pack2(0.f, 0.f);

    const ull* wop = (const ull*)g_Wop;
    #pragma unroll 4
    for (int ep = 0; ep < E_ / 2; ++ep) {
        ull wp = wop[ep * V_ + v];
        #pragma unroll
        for (int r = 0; r < 4; ++r)
            acc[r] = ffma2(((const ull*)av4[r])[ep], wp, acc[r]);
    }

    float lg[4], wb = Wob[v];
    #pragma unroll
    for (int r = 0; r < 4; ++r) {
        float lo, hi; unpack2(acc[r], lo, hi);
        lg[r] = lo + hi + wb;
    }

    float wm[4];
    #pragma unroll
    for (int r = 0; r < 4; ++r) {
        wm[r] = lg[r];
        #pragma unroll
        for (int off = 16; off; off >>= 1)
            wm[r] = fmaxf(wm[r], __shfl_xor_sync(0xffffffffu, wm[r], off));
    }
    if (lane == 0) {
        #pragma unroll
        for (int r = 0; r < 4; ++r) redm[r][wid] = wm[r];
    }
    __syncthreads();
    float bm[4];
    #pragma unroll
    for (int r = 0; r < 4; ++r)
        bm[r] = fmaxf(fmaxf(redm[r][0], redm[r][1]), fmaxf(redm[r][2], redm[r][3]));

    float ws[4];
    #pragma unroll
    for (int r = 0; r < 4; ++r) {
        ws[r] = expf(lg[r] - bm[r]);
        #pragma unroll
        for (int off = 16; off; off >>= 1)
            ws[r] += __shfl_xor_sync(0xffffffffu, ws[r], off);
    }
    if (lane == 0) {
        #pragma unroll
        for (int r = 0; r < 4; ++r) reds[r][wid] = ws[r];
    }
    __syncthreads();

    #pragma unroll
    for (int r = 0; r < 4; ++r) {
        float bs = reds[r][0] + reds[r][1] + reds[r][2] + reds[r][3];
        out[(row0 + r) * V_ + v] = lg[r] - bm[r] - logf(bs);
    }
}

// ---------------------------------------------------------------------------
// kernel_launch
// ---------------------------------------------------------------------------
extern "C" void kernel_launch(void* const* d_in, const int* in_sizes, int n_in,
                              void* d_out, int out_size) {
    int li = 2;
    for (int i = 0; i < n_in; ++i)
        if (in_sizes[i] == 1024) { li = i; break; }

    const float *enc, *dec, *emb, *cw, *cb, *Ww, *Wb, *Wo, *Wob;
    const int* labels;
    if (li == 2) {
        enc = (const float*)d_in[0]; dec = (const float*)d_in[1];
        labels = (const int*)d_in[2];
        emb = (const float*)d_in[3]; cw  = (const float*)d_in[4];
        cb  = (const float*)d_in[5]; Ww  = (const float*)d_in[6];
        Wb  = (const float*)d_in[7]; Wo  = (const float*)d_in[8];
        Wob = (const float*)d_in[9];
    } else {
        enc = (const float*)d_in[0]; dec = (const float*)d_in[1];
        emb = (const float*)d_in[2]; cw  = (const float*)d_in[3];
        cb  = (const float*)d_in[4]; Ww  = (const float*)d_in[5];
        Wb  = (const float*)d_in[6]; Wo  = (const float*)d_in[7];
        Wob = (const float*)d_in[8];
        labels = (const int*)d_in[9];
    }
    float* out = (float*)d_out;

    k_setup<<<NB_EMB + NB_RES + NB_PREP + NB_TR, 256>>>(labels, emb, enc, dec,
                                                        Ww, Wo, cw, cb);

    for (int l = 0; l < NBLK_; ++l) {
        k_conv6<<<384, 256>>>();
        k_glu  <<<BT_, 256>>>();
        k_hgemm<<<256, 128>>>();
        k_attn3<<<128, 512>>>(Wb);
    }

    k_logits<<<BT_ / 4, 128>>>(Wob, out);
}